// round 16
// baseline (speedup 1.0000x reference)
#include <cuda_runtime.h>
#include <cuda_fp16.h>
#include <cstdint>

// CachedMPS on GB300 — fp16 m16n8k16 split HMMA chain, paired steps.
// R16 = R15 with MMA dependency-depth reduction: per ci, main term (hi*bhi)
// and correction terms (hi*blo + lo*bhi) accumulate in SEPARATE banks
// (16 independent chains of depth <=4, was 8 of depth 6), fold
// acc (+)= sc[ci]*(Pm+Pc); acc reused as fold target (dead after split).
// Arithmetic otherwise identical: exact split hi = v & 0xFFFFE000,
// lo = v - hi; W x64 in prep; renormalize to 256 every 2 pairs; final
// eps-free unit-normalize.

#define DEV_INLINE __device__ __forceinline__

static constexpr int D     = 32;
static constexpr int L     = 256;
static constexpr int NPAIR = 127;
static constexpr int C     = 10;
static constexpr int TPB   = 128;             // 4 warps x 16 rows = 64 rows/CTA
static constexpr int ROWS_PER_CTA = 64;
static constexpr float HALF_PI = 1.57079632679489662f;
static constexpr float W_SCALE  = 64.0f;
static constexpr float NORM_TGT = 256.0f;
static constexpr unsigned H_MASK = 0xFFFFE000u;

// composite-W scratch: [NPAIR][4096] u32 (f16x2-packed hi/lo, frag-native)
__device__ unsigned g_Bt[(size_t)NPAIR * 4096];

DEV_INLINE unsigned smem_u32(const void* p) {
    unsigned r;
    asm("{ .reg .u64 t; cvta.to.shared.u64 t, %1; cvt.u32.u64 %0, t; }" : "=r"(r) : "l"(p));
    return r;
}
DEV_INLINE void cp16(unsigned dst, const void* src) {
    asm volatile("cp.async.cg.shared.global [%0], [%1], 16;" :: "r"(dst), "l"(src));
}
DEV_INLINE void cp_commit() { asm volatile("cp.async.commit_group;"); }
DEV_INLINE void cp_wait0()  { asm volatile("cp.async.wait_group 0;" ::: "memory"); }
DEV_INLINE void cp_wait1()  { asm volatile("cp.async.wait_group 1;" ::: "memory"); }

DEV_INLINE unsigned packh2(float lo, float hi) {
    unsigned r; asm("cvt.rn.f16x2.f32 %0, %1, %2;" : "=r"(r) : "f"(hi), "f"(lo));
    return r;
}

DEV_INLINE void mma16(float* c, const unsigned* a, unsigned b0, unsigned b1) {
    asm("mma.sync.aligned.m16n8k16.row.col.f32.f16.f16.f32 "
        "{%0,%1,%2,%3}, {%4,%5,%6,%7}, {%8,%9}, {%0,%1,%2,%3};"
        : "+f"(c[0]), "+f"(c[1]), "+f"(c[2]), "+f"(c[3])
        : "r"(a[0]), "r"(a[1]), "r"(a[2]), "r"(a[3]), "r"(b0), "r"(b1));
}

DEV_INLINE void msplit(float v, float& hf, float& lf) {
    const unsigned h = __float_as_uint(v) & H_MASK;
    hf = __uint_as_float(h);
    lf = v - hf;
}

// ---- prep: composite pair products x64 -> f16 hi/lo, B-frag-native ----
// (layout verified R10/R12/R13)
__global__ void prep_pairs(const float* __restrict__ cores_mid) {
    __shared__ float sW0[2048], sW1[2048];
    const int p = blockIdx.x;
    const float* s0 = cores_mid + (size_t)(2 * p) * 2048;
    const float* s1 = cores_mid + (size_t)(2 * p + 1) * 2048;
    for (int i = threadIdx.x; i < 2048; i += blockDim.x) { sW0[i] = s0[i]; sW1[i] = s1[i]; }
    __syncthreads();

    unsigned* dst = g_Bt + (size_t)p * 4096;
    for (int i = threadIdx.x; i < 4096; i += blockDim.x) {
        const int s = i & 3, lane = (i >> 2) & 31, tj = i >> 7;
        const int T = tj >> 2, j = tj & 3;
        const int q = lane & 3, g = lane >> 2;
        const int reg = s & 1, term = s >> 1;
        const int k0 = 16 * T + 2 * q + 8 * reg;
        const int n  = 8 * j + g;

        float v[2];
        #pragma unroll
        for (int e = 0; e < 2; e++) {
            const int k = k0 + e, ci = k >> 5, a = k & 31;
            const float* r0 = sW0 + (ci & 1) * 1024 + a * 32;
            const float* r1 = sW1 + (ci >> 1) * 1024 + n;
            float acc = 0.f;
            #pragma unroll 8
            for (int cc = 0; cc < 32; cc++) acc += r0[cc] * r1[cc * 32];
            v[e] = acc * W_SCALE;
        }
        float h0, l0, h1, l1;
        msplit(v[0], h0, l0);
        msplit(v[1], h1, l1);
        dst[i] = (term == 0) ? packh2(h0, h1) : packh2(l0, l1);
    }
}

__global__ void __launch_bounds__(TPB, 4)
mps_hmma_kernel(const float* __restrict__ x,
                const float* __restrict__ core0,
                const float* __restrict__ coreN,
                float* __restrict__ out, int B)
{
    __shared__ __align__(16) unsigned sW[2][4096];   // 2 stages x 16KB

    const int tid  = threadIdx.x;
    const int lane = tid & 31;
    const int w    = tid >> 5;
    const int q    = lane & 3;
    const int g    = lane >> 2;
    const int rowbase = blockIdx.x * ROWS_PER_CTA + w * 16;

    int rows[2];
    rows[0] = min(rowbase + g,     B - 1);
    rows[1] = min(rowbase + g + 8, B - 1);

    // prefetch pair-0 tile (16KB)
    {
        const unsigned* gsrc = g_Bt;
        const unsigned sb = smem_u32(&sW[0][0]);
        #pragma unroll
        for (int i = 0; i < 8; i++) {
            const int idx = tid + i * TPB;
            cp16(sb + idx * 16, gsrc + idx * 4);
        }
        cp_commit();
    }

    // ---- init acc = M0 (c-frag layout), then normalize to NORM_TGT ----
    float acc[16];
    #pragma unroll
    for (int rs = 0; rs < 2; rs++) {
        float s0, c0;
        __sincosf(HALF_PI * __ldg(x + (size_t)rows[rs] * L), &s0, &c0);
        #pragma unroll
        for (int j = 0; j < 4; j++)
            #pragma unroll
            for (int pp = 0; pp < 2; pp++) {
                const int col = 8 * j + 2 * q + pp;
                acc[4 * j + 2 * rs + pp] = c0 * core0[col] + s0 * core0[32 + col];
            }
    }
    #pragma unroll
    for (int rs = 0; rs < 2; rs++) {
        float ss = 0.f;
        #pragma unroll
        for (int j = 0; j < 4; j++) {
            const float v0 = acc[4 * j + 2 * rs];
            const float v1 = acc[4 * j + 2 * rs + 1];
            ss += v0 * v0 + v1 * v1;
        }
        ss += __shfl_xor_sync(0xffffffffu, ss, 1);
        ss += __shfl_xor_sync(0xffffffffu, ss, 2);
        const float r = NORM_TGT * rsqrtf(ss);
        #pragma unroll
        for (int j = 0; j < 4; j++) {
            acc[4 * j + 2 * rs]     *= r;
            acc[4 * j + 2 * rs + 1] *= r;
        }
    }

    // pair-0 scalars
    float sc[4][2];
    #pragma unroll
    for (int rs = 0; rs < 2; rs++) {
        float s1v, c1v, s2v, c2v;
        __sincosf(HALF_PI * __ldg(x + (size_t)rows[rs] * L + 1), &s1v, &c1v);
        __sincosf(HALF_PI * __ldg(x + (size_t)rows[rs] * L + 2), &s2v, &c2v);
        sc[0][rs] = c1v * c2v;  sc[1][rs] = s1v * c2v;
        sc[2][rs] = c1v * s2v;  sc[3][rs] = s1v * s2v;
    }

    cp_wait0();
    __syncthreads();

    // ---- 127 composite steps (R15 pipeline: barrier after MMA block) ----
    for (int p = 0; p < NPAIR; p++) {
        if (p + 1 < NPAIR) {
            const unsigned* gsrc = g_Bt + (size_t)(p + 1) * 4096;
            const unsigned sb = smem_u32(&sW[(p + 1) & 1][0]);
            #pragma unroll
            for (int i = 0; i < 8; i++) {
                const int idx = tid + i * TPB;
                cp16(sb + idx * 16, gsrc + idx * 4);
            }
            cp_commit();
            cp_wait1();       // stage p arrived; p+1 still in flight
        } else {
            cp_wait0();
        }

        const unsigned* W = &sW[p & 1][0];

        // split A ONCE (unscaled); acc is dead afterwards (fold target)
        unsigned ahi[2][4], alo[2][4];
        #pragma unroll
        for (int tk = 0; tk < 2; tk++)
            #pragma unroll
            for (int i = 0; i < 4; i++) {
                float h0, l0, h1, l1;
                msplit(acc[8 * tk + 2 * i],     h0, l0);
                msplit(acc[8 * tk + 2 * i + 1], h1, l1);
                ahi[tk][i] = packh2(h0, h1);
                alo[tk][i] = packh2(l0, l1);
            }

        float Pm[2][16], Pc[2][16];   // main / correction banks, ci-parity

        #pragma unroll
        for (int ci = 0; ci < 4; ci++) {
            const int pi = ci & 1;
            #pragma unroll
            for (int k = 0; k < 16; k++) { Pm[pi][k] = 0.f; Pc[pi][k] = 0.f; }

            #pragma unroll
            for (int tk = 0; tk < 2; tk++) {
                const int T = 2 * ci + tk;
                #pragma unroll
                for (int j = 0; j < 4; j++) {
                    const uint4 b = *reinterpret_cast<const uint4*>(
                        W + ((size_t)(T * 4 + j) * 32 + lane) * 4);
                    mma16(&Pm[pi][4 * j], ahi[tk], b.x, b.y);   // hi*Bhi  (depth 2)
                    mma16(&Pc[pi][4 * j], ahi[tk], b.z, b.w);   // hi*Blo  (depth 4)
                    mma16(&Pc[pi][4 * j], alo[tk], b.x, b.y);   // lo*Bhi
                }
            }

            // fold: acc (+)= sc[ci][rs] * (Pm + Pc)
            const float s0 = sc[ci][0], s1 = sc[ci][1];
            if (ci == 0) {
                #pragma unroll
                for (int j = 0; j < 4; j++) {
                    acc[4 * j + 0] = s0 * (Pm[pi][4 * j + 0] + Pc[pi][4 * j + 0]);
                    acc[4 * j + 1] = s0 * (Pm[pi][4 * j + 1] + Pc[pi][4 * j + 1]);
                    acc[4 * j + 2] = s1 * (Pm[pi][4 * j + 2] + Pc[pi][4 * j + 2]);
                    acc[4 * j + 3] = s1 * (Pm[pi][4 * j + 3] + Pc[pi][4 * j + 3]);
                }
            } else {
                #pragma unroll
                for (int j = 0; j < 4; j++) {
                    acc[4 * j + 0] = fmaf(s0, Pm[pi][4 * j + 0] + Pc[pi][4 * j + 0], acc[4 * j + 0]);
                    acc[4 * j + 1] = fmaf(s0, Pm[pi][4 * j + 1] + Pc[pi][4 * j + 1], acc[4 * j + 1]);
                    acc[4 * j + 2] = fmaf(s1, Pm[pi][4 * j + 2] + Pc[pi][4 * j + 2], acc[4 * j + 2]);
                    acc[4 * j + 3] = fmaf(s1, Pm[pi][4 * j + 3] + Pc[pi][4 * j + 3], acc[4 * j + 3]);
                }
            }
        }

        // last W read done -> barrier here (tails overlap other warps' MMAs)
        __syncthreads();

        // next pair's scalars (x-only)
        if (p + 1 < NPAIR) {
            #pragma unroll
            for (int rs = 0; rs < 2; rs++) {
                float s1v, c1v, s2v, c2v;
                __sincosf(HALF_PI * __ldg(x + (size_t)rows[rs] * L + (2 * p + 3)), &s1v, &c1v);
                __sincosf(HALF_PI * __ldg(x + (size_t)rows[rs] * L + (2 * p + 4)), &s2v, &c2v);
                sc[0][rs] = c1v * c2v;  sc[1][rs] = s1v * c2v;
                sc[2][rs] = c1v * s2v;  sc[3][rs] = s1v * s2v;
            }
        }

        // rescale to NORM_TGT every 2 pairs
        if (p & 1) {
            #pragma unroll
            for (int rs = 0; rs < 2; rs++) {
                float ss = 0.f;
                #pragma unroll
                for (int j = 0; j < 4; j++) {
                    const float v0 = acc[4 * j + 2 * rs];
                    const float v1 = acc[4 * j + 2 * rs + 1];
                    ss += v0 * v0 + v1 * v1;
                }
                ss += __shfl_xor_sync(0xffffffffu, ss, 1);
                ss += __shfl_xor_sync(0xffffffffu, ss, 2);
                const float r = NORM_TGT * rsqrtf(ss);
                #pragma unroll
                for (int j = 0; j < 4; j++) {
                    acc[4 * j + 2 * rs]     *= r;
                    acc[4 * j + 2 * rs + 1] *= r;
                }
            }
        }
    }

    // ---- readout: eps-free unit normalize + coreN contraction ----
    #pragma unroll
    for (int rs = 0; rs < 2; rs++) {
        const int row = rowbase + g + 8 * rs;

        float ss = 0.f;
        #pragma unroll
        for (int j = 0; j < 4; j++) {
            const float v0 = acc[4 * j + 2 * rs];
            const float v1 = acc[4 * j + 2 * rs + 1];
            ss += v0 * v0 + v1 * v1;
        }
        ss += __shfl_xor_sync(0xffffffffu, ss, 1);
        ss += __shfl_xor_sync(0xffffffffu, ss, 2);
        const float inv = rsqrtf(ss);           // NO eps (R1 lesson)

        float sL, cL;
        __sincosf(HALF_PI * __ldg(x + (size_t)rows[rs] * L + (L - 1)), &sL, &cL);

        float lg[C];
        #pragma unroll
        for (int cc = 0; cc < C; cc++) lg[cc] = 0.f;
        #pragma unroll
        for (int j = 0; j < 4; j++)
            #pragma unroll
            for (int pp = 0; pp < 2; pp++) {
                const int col = 8 * j + 2 * q + pp;
                const float m = acc[4 * j + 2 * rs + pp];
                #pragma unroll
                for (int cc = 0; cc < C; cc++) {
                    const float wv = cL * coreN[col * C + cc]
                                   + sL * coreN[D * C + col * C + cc];
                    lg[cc] += m * wv;
                }
            }
        #pragma unroll
        for (int cc = 0; cc < C; cc++) {
            lg[cc] += __shfl_xor_sync(0xffffffffu, lg[cc], 1);
            lg[cc] += __shfl_xor_sync(0xffffffffu, lg[cc], 2);
        }
        if (q == 0 && row < B) {
            #pragma unroll
            for (int cc = 0; cc < C; cc++)
                out[(size_t)row * C + cc] = lg[cc] * inv;
        }
    }
}

extern "C" void kernel_launch(void* const* d_in, const int* in_sizes, int n_in,
                              void* d_out, int out_size)
{
    const float* x         = (const float*)d_in[0];
    const float* core0     = (const float*)d_in[1];
    const float* cores_mid = (const float*)d_in[2];
    const float* coreN     = (const float*)d_in[3];
    float* out = (float*)d_out;

    const int B = in_sizes[0] / L;
    const int grid = (B + ROWS_PER_CTA - 1) / ROWS_PER_CTA;   // 512 for B=32768

    prep_pairs<<<NPAIR, 256>>>(cores_mid);
    mps_hmma_kernel<<<grid, TPB>>>(x, core0, coreN, out, B);
}

// round 17
// speedup vs baseline: 1.1194x; 1.1194x over previous
#include <cuda_runtime.h>
#include <cuda_fp16.h>
#include <cstdint>

// CachedMPS on GB300 — fp16 m16n8k16 split HMMA chain, paired steps.
// R17 = R15 arithmetic with HALF the barriers: 3-stage cp.async ring,
// TPB=256 (8 warps), two pairs processed per __syncthreads. Staged waits:
// wait_group(2) before pair 2t (stage issued a full iteration earlier),
// wait_group(1) before pair 2t+1 (issued post-barrier last iteration).
// Arithmetic identical to R13/R15: exact split hi = v & 0xFFFFE000,
// lo = v - hi; P[ci] = M x W[ci]; post-hoc fold acc = sum sc[ci]*P[ci];
// W x64 in prep; renormalize to 256 every 2 pairs; eps-free final normalize.

#define DEV_INLINE __device__ __forceinline__

static constexpr int D     = 32;
static constexpr int L     = 256;
static constexpr int NPAIR = 127;
static constexpr int C     = 10;
static constexpr int TPB   = 256;             // 8 warps x 16 rows = 128 rows/CTA
static constexpr int ROWS_PER_CTA = 128;
static constexpr float HALF_PI = 1.57079632679489662f;
static constexpr float W_SCALE  = 64.0f;
static constexpr float NORM_TGT = 256.0f;
static constexpr unsigned H_MASK = 0xFFFFE000u;

// composite-W scratch: [NPAIR][4096] u32 (f16x2-packed hi/lo, frag-native)
__device__ unsigned g_Bt[(size_t)NPAIR * 4096];

DEV_INLINE unsigned smem_u32(const void* p) {
    unsigned r;
    asm("{ .reg .u64 t; cvta.to.shared.u64 t, %1; cvt.u32.u64 %0, t; }" : "=r"(r) : "l"(p));
    return r;
}
DEV_INLINE void cp16(unsigned dst, const void* src) {
    asm volatile("cp.async.cg.shared.global [%0], [%1], 16;" :: "r"(dst), "l"(src));
}
DEV_INLINE void cp_commit() { asm volatile("cp.async.commit_group;"); }
DEV_INLINE void cp_wait0()  { asm volatile("cp.async.wait_group 0;" ::: "memory"); }
DEV_INLINE void cp_wait1()  { asm volatile("cp.async.wait_group 1;" ::: "memory"); }
DEV_INLINE void cp_wait2()  { asm volatile("cp.async.wait_group 2;" ::: "memory"); }

DEV_INLINE unsigned packh2(float lo, float hi) {
    unsigned r; asm("cvt.rn.f16x2.f32 %0, %1, %2;" : "=r"(r) : "f"(hi), "f"(lo));
    return r;
}

DEV_INLINE void mma16(float* c, const unsigned* a, unsigned b0, unsigned b1) {
    asm("mma.sync.aligned.m16n8k16.row.col.f32.f16.f16.f32 "
        "{%0,%1,%2,%3}, {%4,%5,%6,%7}, {%8,%9}, {%0,%1,%2,%3};"
        : "+f"(c[0]), "+f"(c[1]), "+f"(c[2]), "+f"(c[3])
        : "r"(a[0]), "r"(a[1]), "r"(a[2]), "r"(a[3]), "r"(b0), "r"(b1));
}

DEV_INLINE void msplit(float v, float& hf, float& lf) {
    const unsigned h = __float_as_uint(v) & H_MASK;
    hf = __uint_as_float(h);
    lf = v - hf;
}

// ---- prep: composite pair products x64 -> f16 hi/lo, B-frag-native ----
// (layout verified R10/R12/R13) Parallelized 2x: grid = 2*NPAIR.
__global__ void prep_pairs(const float* __restrict__ cores_mid) {
    __shared__ float sW0[2048], sW1[2048];
    const int p    = blockIdx.x >> 1;
    const int half = blockIdx.x & 1;
    const float* s0 = cores_mid + (size_t)(2 * p) * 2048;
    const float* s1 = cores_mid + (size_t)(2 * p + 1) * 2048;
    for (int i = threadIdx.x; i < 2048; i += blockDim.x) { sW0[i] = s0[i]; sW1[i] = s1[i]; }
    __syncthreads();

    unsigned* dst = g_Bt + (size_t)p * 4096;
    const int i0 = half * 2048;
    for (int i = i0 + threadIdx.x; i < i0 + 2048; i += blockDim.x) {
        const int s = i & 3, lane = (i >> 2) & 31, tj = i >> 7;
        const int T = tj >> 2, j = tj & 3;
        const int q = lane & 3, g = lane >> 2;
        const int reg = s & 1, term = s >> 1;
        const int k0 = 16 * T + 2 * q + 8 * reg;
        const int n  = 8 * j + g;

        float v[2];
        #pragma unroll
        for (int e = 0; e < 2; e++) {
            const int k = k0 + e, ci = k >> 5, a = k & 31;
            const float* r0 = sW0 + (ci & 1) * 1024 + a * 32;
            const float* r1 = sW1 + (ci >> 1) * 1024 + n;
            float acc = 0.f;
            #pragma unroll 8
            for (int cc = 0; cc < 32; cc++) acc += r0[cc] * r1[cc * 32];
            v[e] = acc * W_SCALE;
        }
        float h0, l0, h1, l1;
        msplit(v[0], h0, l0);
        msplit(v[1], h1, l1);
        dst[i] = (term == 0) ? packh2(h0, h1) : packh2(l0, l1);
    }
}

__global__ void __launch_bounds__(TPB, 2)
mps_hmma_kernel(const float* __restrict__ x,
                const float* __restrict__ core0,
                const float* __restrict__ coreN,
                float* __restrict__ out, int B)
{
    __shared__ __align__(16) unsigned sW[3][4096];   // 3-stage ring, 48KB

    const int tid  = threadIdx.x;
    const int lane = tid & 31;
    const int w    = tid >> 5;
    const int q    = lane & 3;
    const int g    = lane >> 2;
    const int rowbase = blockIdx.x * ROWS_PER_CTA + w * 16;

    int rows[2];
    rows[0] = min(rowbase + g,     B - 1);
    rows[1] = min(rowbase + g + 8, B - 1);

    // issue one stage into its ring slot (empty commit keeps group count fixed)
    auto issue_stage = [&](int s) {
        if (s < NPAIR) {
            const unsigned* gsrc = g_Bt + (size_t)s * 4096;
            const unsigned sb = smem_u32(&sW[s % 3][0]);
            #pragma unroll
            for (int i = 0; i < 4; i++) {
                const int idx = tid + i * TPB;
                cp16(sb + idx * 16, gsrc + idx * 4);
            }
        }
        cp_commit();
    };

    issue_stage(0);
    issue_stage(1);

    // ---- init acc = M0 (c-frag layout), then normalize to NORM_TGT ----
    float acc[16];
    #pragma unroll
    for (int rs = 0; rs < 2; rs++) {
        float s0, c0;
        __sincosf(HALF_PI * __ldg(x + (size_t)rows[rs] * L), &s0, &c0);
        #pragma unroll
        for (int j = 0; j < 4; j++)
            #pragma unroll
            for (int pp = 0; pp < 2; pp++) {
                const int col = 8 * j + 2 * q + pp;
                acc[4 * j + 2 * rs + pp] = c0 * core0[col] + s0 * core0[32 + col];
            }
    }
    #pragma unroll
    for (int rs = 0; rs < 2; rs++) {
        float ss = 0.f;
        #pragma unroll
        for (int j = 0; j < 4; j++) {
            const float v0 = acc[4 * j + 2 * rs];
            const float v1 = acc[4 * j + 2 * rs + 1];
            ss += v0 * v0 + v1 * v1;
        }
        ss += __shfl_xor_sync(0xffffffffu, ss, 1);
        ss += __shfl_xor_sync(0xffffffffu, ss, 2);
        const float r = NORM_TGT * rsqrtf(ss);
        #pragma unroll
        for (int j = 0; j < 4; j++) {
            acc[4 * j + 2 * rs]     *= r;
            acc[4 * j + 2 * rs + 1] *= r;
        }
    }

    // pair scalars for two pairs: scP[sel][ci][rs]
    float scP[2][4][2];
    auto calc_sc = [&](int pr, int sel) {
        if (pr < NPAIR) {
            #pragma unroll
            for (int rs = 0; rs < 2; rs++) {
                float s1v, c1v, s2v, c2v;
                __sincosf(HALF_PI * __ldg(x + (size_t)rows[rs] * L + (2 * pr + 1)), &s1v, &c1v);
                __sincosf(HALF_PI * __ldg(x + (size_t)rows[rs] * L + (2 * pr + 2)), &s2v, &c2v);
                scP[sel][0][rs] = c1v * c2v;  scP[sel][1][rs] = s1v * c2v;
                scP[sel][2][rs] = c1v * s2v;  scP[sel][3][rs] = s1v * s2v;
            }
        }
    };
    calc_sc(0, 0);
    calc_sc(1, 1);

    // stage 0 fully visible across all threads before the loop
    cp_wait1();
    __syncthreads();

    // one pair: split acc -> P[ci] MMAs -> fold back into acc
    auto proc_pair = [&](const unsigned* W, const float (&scp)[4][2]) {
        unsigned ahi[2][4], alo[2][4];
        #pragma unroll
        for (int tk = 0; tk < 2; tk++)
            #pragma unroll
            for (int i = 0; i < 4; i++) {
                float h0, l0, h1, l1;
                msplit(acc[8 * tk + 2 * i],     h0, l0);
                msplit(acc[8 * tk + 2 * i + 1], h1, l1);
                ahi[tk][i] = packh2(h0, h1);
                alo[tk][i] = packh2(l0, l1);
            }

        float P0[16], P1[16];
        #pragma unroll
        for (int ci = 0; ci < 4; ci++) {
            float* P = (ci & 1) ? P1 : P0;
            #pragma unroll
            for (int k = 0; k < 16; k++) P[k] = 0.f;

            #pragma unroll
            for (int tk = 0; tk < 2; tk++) {
                const int T = 2 * ci + tk;
                #pragma unroll
                for (int j = 0; j < 4; j++) {
                    const uint4 b = *reinterpret_cast<const uint4*>(
                        W + ((size_t)(T * 4 + j) * 32 + lane) * 4);
                    mma16(&P[4 * j], ahi[tk], b.x, b.y);   // hi*Bhi
                    mma16(&P[4 * j], ahi[tk], b.z, b.w);   // hi*Blo
                    mma16(&P[4 * j], alo[tk], b.x, b.y);   // lo*Bhi
                }
            }

            const float s0 = scp[ci][0], s1 = scp[ci][1];
            if (ci == 0) {
                #pragma unroll
                for (int j = 0; j < 4; j++) {
                    acc[4 * j + 0] = s0 * P[4 * j + 0];
                    acc[4 * j + 1] = s0 * P[4 * j + 1];
                    acc[4 * j + 2] = s1 * P[4 * j + 2];
                    acc[4 * j + 3] = s1 * P[4 * j + 3];
                }
            } else {
                #pragma unroll
                for (int j = 0; j < 4; j++) {
                    acc[4 * j + 0] = fmaf(s0, P[4 * j + 0], acc[4 * j + 0]);
                    acc[4 * j + 1] = fmaf(s0, P[4 * j + 1], acc[4 * j + 1]);
                    acc[4 * j + 2] = fmaf(s1, P[4 * j + 2], acc[4 * j + 2]);
                    acc[4 * j + 3] = fmaf(s1, P[4 * j + 3], acc[4 * j + 3]);
                }
            }
        }
    };

    auto rescale = [&]() {
        #pragma unroll
        for (int rs = 0; rs < 2; rs++) {
            float ss = 0.f;
            #pragma unroll
            for (int j = 0; j < 4; j++) {
                const float v0 = acc[4 * j + 2 * rs];
                const float v1 = acc[4 * j + 2 * rs + 1];
                ss += v0 * v0 + v1 * v1;
            }
            ss += __shfl_xor_sync(0xffffffffu, ss, 1);
            ss += __shfl_xor_sync(0xffffffffu, ss, 2);
            const float r = NORM_TGT * rsqrtf(ss);
            #pragma unroll
            for (int j = 0; j < 4; j++) {
                acc[4 * j + 2 * rs]     *= r;
                acc[4 * j + 2 * rs + 1] *= r;
            }
        }
    };

    // ---- 63 iterations x 2 pairs (pairs 0..125), then pair 126 ----
    for (int t = 0; t < 63; t++) {
        const int p0 = 2 * t;
        issue_stage(p0 + 2);
        cp_wait2();                              // stage p0 arrived
        proc_pair(&sW[p0 % 3][0], scP[0]);
        cp_wait1();                              // stage p0+1 arrived
        proc_pair(&sW[(p0 + 1) % 3][0], scP[1]);
        __syncthreads();                         // ONE barrier per 2 pairs
        issue_stage(p0 + 3);
        calc_sc(p0 + 2, 0);
        calc_sc(p0 + 3, 1);
        rescale();                               // cadence: every 2 pairs
    }
    cp_wait0();
    proc_pair(&sW[126 % 3][0], scP[0]);          // final pair (acc at 256-scale)

    // ---- readout: eps-free unit normalize + coreN contraction ----
    #pragma unroll
    for (int rs = 0; rs < 2; rs++) {
        const int row = rowbase + g + 8 * rs;

        float ss = 0.f;
        #pragma unroll
        for (int j = 0; j < 4; j++) {
            const float v0 = acc[4 * j + 2 * rs];
            const float v1 = acc[4 * j + 2 * rs + 1];
            ss += v0 * v0 + v1 * v1;
        }
        ss += __shfl_xor_sync(0xffffffffu, ss, 1);
        ss += __shfl_xor_sync(0xffffffffu, ss, 2);
        const float inv = rsqrtf(ss);           // NO eps (R1 lesson)

        float sL, cL;
        __sincosf(HALF_PI * __ldg(x + (size_t)rows[rs] * L + (L - 1)), &sL, &cL);

        float lg[C];
        #pragma unroll
        for (int cc = 0; cc < C; cc++) lg[cc] = 0.f;
        #pragma unroll
        for (int j = 0; j < 4; j++)
            #pragma unroll
            for (int pp = 0; pp < 2; pp++) {
                const int col = 8 * j + 2 * q + pp;
                const float m = acc[4 * j + 2 * rs + pp];
                #pragma unroll
                for (int cc = 0; cc < C; cc++) {
                    const float wv = cL * coreN[col * C + cc]
                                   + sL * coreN[D * C + col * C + cc];
                    lg[cc] += m * wv;
                }
            }
        #pragma unroll
        for (int cc = 0; cc < C; cc++) {
            lg[cc] += __shfl_xor_sync(0xffffffffu, lg[cc], 1);
            lg[cc] += __shfl_xor_sync(0xffffffffu, lg[cc], 2);
        }
        if (q == 0 && row < B) {
            #pragma unroll
            for (int cc = 0; cc < C; cc++)
                out[(size_t)row * C + cc] = lg[cc] * inv;
        }
    }
}

extern "C" void kernel_launch(void* const* d_in, const int* in_sizes, int n_in,
                              void* d_out, int out_size)
{
    const float* x         = (const float*)d_in[0];
    const float* core0     = (const float*)d_in[1];
    const float* cores_mid = (const float*)d_in[2];
    const float* coreN     = (const float*)d_in[3];
    float* out = (float*)d_out;

    const int B = in_sizes[0] / L;
    const int grid = (B + ROWS_PER_CTA - 1) / ROWS_PER_CTA;   // 256 for B=32768

    prep_pairs<<<2 * NPAIR, 256>>>(cores_mid);
    mps_hmma_kernel<<<grid, TPB>>>(x, core0, coreN, out, B);
}